// round 1
// baseline (speedup 1.0000x reference)
#include <cuda_runtime.h>
#include <math.h>
#include <stdint.h>

#define NND   4096
#define KNBR  9
#define INC   32
#define OUTC  64
#define HID   128
#define SDIM  4096   // HID * INC

// ---------------- scratch (static device globals; no allocation) ----------------
__device__ float g_sqpos[NND];
__device__ float g_sqx[NND];
__device__ int   g_idx[2][NND * KNBR];
__device__ float g_S[2][(size_t)NND * SDIM];      // 2 x 64 MB
__device__ float g_xjm[2][NND * INC];

// ---------------- 1) squared norms (same fmaf order as knn dot -> exact self-dist 0)
__global__ void sq_kernel(const float* __restrict__ pos, const float* __restrict__ x) {
    int i = blockIdx.x * blockDim.x + threadIdx.x;
    if (i >= NND) return;
    float s = 0.f;
#pragma unroll
    for (int d = 0; d < 3; d++) { float v = pos[i * 3 + d]; s = fmaf(v, v, s); }
    g_sqpos[i] = s;
    float s2 = 0.f;
#pragma unroll
    for (int d = 0; d < INC; d++) { float v = x[i * INC + d]; s2 = fmaf(v, v, s2); }
    g_sqx[i] = s2;
}

// ---------------- 2) brute-force KNN: one warp per query, top-9 in registers ----
// Order matches jax.lax.top_k(-d): ascending d, ties -> ascending index.
__device__ __forceinline__ bool knn_less(float d, int i, float d2, int i2) {
    return (d < d2) || (d == d2 && i < i2);
}

template <int BR>  // BR=0: pos (dim 3), BR=1: x (dim 32)
__global__ __launch_bounds__(256) void knn_kernel(const float* __restrict__ f) {
    const int DIM = BR ? INC : 3;
    const float* __restrict__ sq = BR ? g_sqx : g_sqpos;
    int* __restrict__ oidx = g_idx[BR];

    __shared__ float s_d[8][32 * KNBR];
    __shared__ int   s_i[8][32 * KNBR];

    int w = threadIdx.x >> 5, lane = threadIdx.x & 31;
    int q = blockIdx.x * 8 + w;

    // query vector in registers (all lanes identical; broadcast loads)
    float qv[32];
#pragma unroll
    for (int d = 0; d < 32; d++) qv[d] = (d < DIM) ? f[q * DIM + d] : 0.f;
    float sqq = sq[q];

    float bd[KNBR]; int bi[KNBR];
#pragma unroll
    for (int r = 0; r < KNBR; r++) { bd[r] = 3.4e38f; bi[r] = 0x7FFFFFFF; }

    for (int j = lane; j < NND; j += 32) {
        float acc = 0.f;
        if (BR) {
            const float4* row = reinterpret_cast<const float4*>(f + (size_t)j * 32);
#pragma unroll
            for (int m = 0; m < 8; m++) {
                float4 c = __ldg(&row[m]);
                acc = fmaf(qv[m * 4 + 0], c.x, acc);
                acc = fmaf(qv[m * 4 + 1], c.y, acc);
                acc = fmaf(qv[m * 4 + 2], c.z, acc);
                acc = fmaf(qv[m * 4 + 3], c.w, acc);
            }
        } else {
#pragma unroll
            for (int d = 0; d < 3; d++) acc = fmaf(qv[d], __ldg(&f[j * 3 + d]), acc);
        }
        float dist = (sqq + sq[j]) - 2.0f * acc;
        if (knn_less(dist, j, bd[KNBR - 1], bi[KNBR - 1])) {
            float cd = dist; int ci = j;
#pragma unroll
            for (int r = 0; r < KNBR; r++) {
                bool sw = knn_less(cd, ci, bd[r], bi[r]);
                float td = bd[r]; int ti = bi[r];
                if (sw) { bd[r] = cd; bi[r] = ci; cd = td; ci = ti; }
            }
        }
    }

    // dump sorted per-lane lists, then 9 rounds of warp-wide argmin merge
#pragma unroll
    for (int r = 0; r < KNBR; r++) { s_d[w][lane * KNBR + r] = bd[r]; s_i[w][lane * KNBR + r] = bi[r]; }
    __syncwarp();

    int p = 0;
    for (int r = 0; r < KNBR; r++) {
        float cd = (p < KNBR) ? s_d[w][lane * KNBR + p] : 3.4e38f;
        int   ci = (p < KNBR) ? s_i[w][lane * KNBR + p] : 0x7FFFFFFF;
        float rd = cd; int ri = ci;
#pragma unroll
        for (int off = 16; off; off >>= 1) {
            float od = __shfl_xor_sync(0xFFFFFFFFu, rd, off);
            int   oi = __shfl_xor_sync(0xFFFFFFFFu, ri, off);
            if (knn_less(od, oi, rd, ri)) { rd = od; ri = oi; }
        }
        if (ci == ri && p < KNBR) p++;   // candidate indices are unique per lane
        if (lane == 0) oidx[q * KNBR + r] = ri;
    }
}

// ---------------- 3) per-(node, branch): attrs -> h -> S, xjmean ---------------
__global__ __launch_bounds__(128) void buildS_kernel(
    const float* __restrict__ x, const float* __restrict__ pos,
    const float* __restrict__ w1g, const float* __restrict__ b1g,
    const float* __restrict__ w1f, const float* __restrict__ b1f) {
    int n = blockIdx.x, br = blockIdx.y;
    int t = threadIdx.x;  // 128

    __shared__ int   s_idx[KNBR];
    __shared__ float s_xj[KNBR][INC];
    __shared__ float s_attr[KNBR][3];
    __shared__ float s_h[KNBR][HID];
    __shared__ float s_pn[3];

    const int* idx = g_idx[br];
    const float* w1 = br ? w1f : w1g;
    const float* b1 = br ? b1f : b1g;

    if (t < KNBR) s_idx[t] = idx[n * KNBR + t];
    if (t < 3)    s_pn[t] = pos[n * 3 + t];
    __syncthreads();

    for (int v = t; v < KNBR * INC; v += 128)
        s_xj[v / INC][v % INC] = x[(size_t)s_idx[v / INC] * INC + (v % INC)];

    if (t < KNBR) {
        int sj = s_idx[t];
        float cx = pos[sj * 3 + 0] - s_pn[0];
        float cy = pos[sj * 3 + 1] - s_pn[1];
        float cz = pos[sj * 3 + 2] - s_pn[2];
        float rho = sqrtf((cx * cx + cy * cy) + cz * cz);
        float th  = atan2f(cy, cx);
        float ratio = cz / fmaxf(rho, 1e-12f);
        ratio = fminf(1.0f, fmaxf(-1.0f, ratio));
        float ph = acosf(ratio);
        s_attr[t][0] = rho; s_attr[t][1] = th; s_attr[t][2] = ph;
    }
    __syncthreads();

    {   // fnet layer 1 + tanh: thread t owns channel c = t
        int c = t;
        float wa = w1[c], wb = w1[HID + c], wc = w1[2 * HID + c], bb = b1[c];
        float hk[KNBR];
#pragma unroll
        for (int k = 0; k < KNBR; k++)
            hk[k] = tanhf(bb + s_attr[k][0] * wa + s_attr[k][1] * wb + s_attr[k][2] * wc);
#pragma unroll
        for (int k = 0; k < KNBR; k++) s_h[k][c] = hk[k];
    }
    __syncthreads();

    // S[c][i] = sum_k h[k][c] * xj[k][i]; coalesced writes (lane = i)
    int w = t >> 5, lane = t & 31;
    float* Sout = g_S[br] + (size_t)n * SDIM;
    for (int j = 0; j < 32; j++) {
        int c = w * 32 + j;
        float s = 0.f;
#pragma unroll
        for (int k = 0; k < KNBR; k++) s = fmaf(s_h[k][c], s_xj[k][lane], s);
        Sout[c * INC + lane] = s;
    }
    if (t < INC) {
        float m = 0.f;
#pragma unroll
        for (int k = 0; k < KNBR; k++) m += s_xj[k][t];
        g_xjm[br][n * INC + t] = m * (1.0f / 9.0f);
    }
}

// ---------------- 4) fused GEMM: out = 0.5*( (Sg@Wg + Sf@Wf)/9 + biasg + biasf )
// Tile: 32 nodes x 64 outputs, 256 threads, each thread 2x4 accumulators, KC=16.
__global__ __launch_bounds__(256) void out_kernel(
    const float* __restrict__ w2g, const float* __restrict__ b2g,
    const float* __restrict__ w2f, const float* __restrict__ b2f,
    float* __restrict__ out) {
    __shared__ float As[16][33];
    __shared__ float Bs[16][64];

    int tid = threadIdx.x;
    int tx = tid & 15, ty = tid >> 4;
    int n0 = blockIdx.x * 32;

    float acc[2][4];
#pragma unroll
    for (int r = 0; r < 2; r++)
#pragma unroll
        for (int c = 0; c < 4; c++) acc[r][c] = 0.f;

    for (int br = 0; br < 2; br++) {
        const float* Sb = g_S[br] + (size_t)n0 * SDIM;
        const float* W  = br ? w2f : w2g;
        for (int k0 = 0; k0 < SDIM; k0 += 16) {
            // stage A (32 x 16, transposed) — 512 elems
#pragma unroll
            for (int v = tid; v < 512; v += 256) {
                int m = v >> 4, kk = v & 15;
                As[kk][m] = Sb[(size_t)m * SDIM + k0 + kk];
            }
            // stage B (16 x 64). k = c*32+i maps to w2[c*2048 + i*64 + o]; within a
            // 16-chunk c is constant, so the 1024 floats are contiguous.
            {
                int c = k0 >> 5;
                int ibase = k0 & 31;
                const float* Wc = W + (size_t)c * 2048 + ibase * 64;
#pragma unroll
                for (int v = tid; v < 1024; v += 256) Bs[v >> 6][v & 63] = Wc[v];
            }
            __syncthreads();
#pragma unroll
            for (int kk = 0; kk < 16; kk++) {
                float a0 = As[kk][ty * 2 + 0];
                float a1 = As[kk][ty * 2 + 1];
                float4 b = *reinterpret_cast<const float4*>(&Bs[kk][tx * 4]);
                acc[0][0] = fmaf(a0, b.x, acc[0][0]);
                acc[0][1] = fmaf(a0, b.y, acc[0][1]);
                acc[0][2] = fmaf(a0, b.z, acc[0][2]);
                acc[0][3] = fmaf(a0, b.w, acc[0][3]);
                acc[1][0] = fmaf(a1, b.x, acc[1][0]);
                acc[1][1] = fmaf(a1, b.y, acc[1][1]);
                acc[1][2] = fmaf(a1, b.z, acc[1][2]);
                acc[1][3] = fmaf(a1, b.w, acc[1][3]);
            }
            __syncthreads();
        }
    }

    // epilogue: /9, + bias (xjmean @ b2, both branches), * 0.5
#pragma unroll
    for (int r = 0; r < 2; r++) {
        int n = n0 + ty * 2 + r;
#pragma unroll
        for (int cidx = 0; cidx < 4; cidx++) {
            int o = tx * 4 + cidx;
            float val = acc[r][cidx] * (1.0f / 9.0f);
#pragma unroll
            for (int br = 0; br < 2; br++) {
                const float* b2 = br ? b2f : b2g;
                const float* xm = g_xjm[br] + (size_t)n * INC;
                for (int i = 0; i < INC; i++)
                    val = fmaf(xm[i], __ldg(&b2[i * 64 + o]), val);
            }
            out[(size_t)n * OUTC + o] = 0.5f * val;
        }
    }
}

// ---------------- launch -------------------------------------------------------
extern "C" void kernel_launch(void* const* d_in, const int* in_sizes, int n_in,
                              void* d_out, int out_size) {
    const float* x   = (const float*)d_in[0];
    const float* pos = (const float*)d_in[1];
    const float* w1g = (const float*)d_in[2];
    const float* b1g = (const float*)d_in[3];
    const float* w2g = (const float*)d_in[4];
    const float* b2g = (const float*)d_in[5];
    const float* w1f = (const float*)d_in[6];
    const float* b1f = (const float*)d_in[7];
    const float* w2f = (const float*)d_in[8];
    const float* b2f = (const float*)d_in[9];
    float* out = (float*)d_out;

    sq_kernel<<<(NND + 255) / 256, 256>>>(pos, x);
    knn_kernel<0><<<NND / 8, 256>>>(pos);
    knn_kernel<1><<<NND / 8, 256>>>(x);
    buildS_kernel<<<dim3(NND, 2), 128>>>(x, pos, w1g, b1g, w1f, b1f);
    out_kernel<<<NND / 32, 256>>>(w2g, b2g, w2f, b2f, out);
}

// round 2
// speedup vs baseline: 2.0073x; 2.0073x over previous
#include <cuda_runtime.h>
#include <math.h>
#include <stdint.h>

#define NND   4096
#define KNBR  9
#define INC   32
#define OUTC  64
#define HID   128
#define SDIM  4096   // HID * INC

// ---------------- scratch (static device globals; no allocation) ----------------
__device__ float g_sqpos[NND];
__device__ float g_sqx[NND];
__device__ int   g_idx[2][NND * KNBR];
__device__ float g_S[2][(size_t)NND * SDIM];          // 2 x 64 MB
__device__ float g_xjm[2][NND * INC];
__device__ float g_part[2 * NND * OUTC];              // per-branch GEMM partials

// ---------------- 1) squared norms (same fmaf order as knn dot) ----------------
__global__ void sq_kernel(const float* __restrict__ pos, const float* __restrict__ x) {
    int i = blockIdx.x * blockDim.x + threadIdx.x;
    if (i >= NND) return;
    float s = 0.f;
#pragma unroll
    for (int d = 0; d < 3; d++) { float v = pos[i * 3 + d]; s = fmaf(v, v, s); }
    g_sqpos[i] = s;
    float s2 = 0.f;
#pragma unroll
    for (int d = 0; d < INC; d++) { float v = x[i * INC + d]; s2 = fmaf(v, v, s2); }
    g_sqx[i] = s2;
}

// Order matches jax.lax.top_k(-d): ascending d, ties -> ascending index.
__device__ __forceinline__ bool knn_less(float d, int i, float d2, int i2) {
    return (d < d2) || (d == d2 && i < i2);
}

__device__ __forceinline__ void knn_insert(float dist, int j, float bd[KNBR], int bi[KNBR]) {
    if (knn_less(dist, j, bd[KNBR - 1], bi[KNBR - 1])) {
        float cd = dist; int ci = j;
#pragma unroll
        for (int r = 0; r < KNBR; r++) {
            bool sw = knn_less(cd, ci, bd[r], bi[r]);
            float td = bd[r]; int ti = bi[r];
            if (sw) { bd[r] = cd; bi[r] = ci; cd = td; ci = ti; }
        }
    }
}

// Warp-wide 9-round merge of per-lane sorted lists (smem-backed, per-warp region).
__device__ __forceinline__ void knn_merge(float* md, int* mi, const float bd[KNBR],
                                          const int bi[KNBR], int lane, int* oidx, int q) {
#pragma unroll
    for (int r = 0; r < KNBR; r++) { md[lane * KNBR + r] = bd[r]; mi[lane * KNBR + r] = bi[r]; }
    __syncwarp();
    int p = 0;
    for (int r = 0; r < KNBR; r++) {
        float cd = (p < KNBR) ? md[lane * KNBR + p] : 3.4e38f;
        int   ci = (p < KNBR) ? mi[lane * KNBR + p] : 0x7FFFFFFF;
        float rd = cd; int ri = ci;
#pragma unroll
        for (int off = 16; off; off >>= 1) {
            float od = __shfl_xor_sync(0xFFFFFFFFu, rd, off);
            int   oi = __shfl_xor_sync(0xFFFFFFFFu, ri, off);
            if (knn_less(od, oi, rd, ri)) { rd = od; ri = oi; }
        }
        if (ci == ri && p < KNBR) p++;   // candidate indices unique per lane
        if (lane == 0) oidx[q * KNBR + r] = ri;
    }
    __syncwarp();
}

// ---------------- 2a) KNN on pos (dim 3): whole pos in smem -------------------
__global__ __launch_bounds__(256) void knn_pos_kernel(const float* __restrict__ pos) {
    __shared__ float smem[NND * 3];   // 48 KB; candidate coords, merge overlay after
    int t = threadIdx.x, w = t >> 5, lane = t & 31;
    int q = blockIdx.x * 8 + w;

    for (int v = t; v < NND * 3; v += 256) smem[v] = pos[v];
    __syncthreads();

    float q0 = pos[q * 3 + 0], q1 = pos[q * 3 + 1], q2 = pos[q * 3 + 2];
    float sqq = g_sqpos[q];

    float bd[KNBR]; int bi[KNBR];
#pragma unroll
    for (int r = 0; r < KNBR; r++) { bd[r] = 3.4e38f; bi[r] = 0x7FFFFFFF; }

    for (int j = lane; j < NND; j += 32) {
        float acc = 0.f;
        acc = fmaf(q0, smem[j * 3 + 0], acc);
        acc = fmaf(q1, smem[j * 3 + 1], acc);
        acc = fmaf(q2, smem[j * 3 + 2], acc);
        float dist = (sqq + g_sqpos[j]) - 2.0f * acc;
        knn_insert(dist, j, bd, bi);
    }
    __syncthreads();   // all warps done reading smem before merge overlay

    float* md = smem + (size_t)w * 288;
    int*   mi = (int*)(smem + 8 * 288) + (size_t)w * 288;
    knn_merge(md, mi, bd, bi, lane, g_idx[0], q);
}

// ---------------- 2b) KNN on x (dim 32): tiled smem, 2 queries/warp -----------
#define TS 256
__global__ __launch_bounds__(256) void knn_feat_kernel(const float* __restrict__ x) {
    __shared__ float s_tile[TS * 33];   // stride-33 pad: conflict-free
    __shared__ float s_sq[TS];
    int t = threadIdx.x, w = t >> 5, lane = t & 31;
    int qa_i = blockIdx.x * 16 + w * 2;
    int qb_i = qa_i + 1;

    float qa[INC], qb[INC];
#pragma unroll
    for (int d = 0; d < INC; d++) qa[d] = x[qa_i * INC + d];
#pragma unroll
    for (int d = 0; d < INC; d++) qb[d] = x[qb_i * INC + d];
    float sqa = g_sqx[qa_i], sqb = g_sqx[qb_i];

    float bda[KNBR], bdb[KNBR]; int bia[KNBR], bib[KNBR];
#pragma unroll
    for (int r = 0; r < KNBR; r++) {
        bda[r] = 3.4e38f; bia[r] = 0x7FFFFFFF;
        bdb[r] = 3.4e38f; bib[r] = 0x7FFFFFFF;
    }

    for (int base = 0; base < NND; base += TS) {
        __syncthreads();
#pragma unroll
        for (int v = t; v < TS * INC; v += 256) {
            int r = v >> 5, d = v & 31;
            s_tile[r * 33 + d] = x[(size_t)(base + r) * INC + d];
        }
        s_sq[t] = g_sqx[base + t];
        __syncthreads();

        for (int s = 0; s < TS; s += 32) {
            int r = s + lane;
            int j = base + r;
            const float* c = &s_tile[r * 33];
            float acc0 = 0.f, acc1 = 0.f;
#pragma unroll
            for (int d = 0; d < INC; d++) {
                float cv = c[d];
                acc0 = fmaf(qa[d], cv, acc0);
                acc1 = fmaf(qb[d], cv, acc1);
            }
            float sqj = s_sq[r];
            knn_insert((sqa + sqj) - 2.0f * acc0, j, bda, bia);
            knn_insert((sqb + sqj) - 2.0f * acc1, j, bdb, bib);
        }
    }
    __syncthreads();   // done with s_tile; safe to overlay merge buffers

    float* md = s_tile + (size_t)w * 288;
    int*   mi = (int*)(s_tile + 8 * 288) + (size_t)w * 288;
    knn_merge(md, mi, bda, bia, lane, g_idx[1], qa_i);
    knn_merge(md, mi, bdb, bib, lane, g_idx[1], qb_i);
}

// ---------------- 3) per-(node, branch): attrs -> h -> S, xjmean ---------------
__global__ __launch_bounds__(128) void buildS_kernel(
    const float* __restrict__ x, const float* __restrict__ pos,
    const float* __restrict__ w1g, const float* __restrict__ b1g,
    const float* __restrict__ w1f, const float* __restrict__ b1f) {
    int n = blockIdx.x, br = blockIdx.y;
    int t = threadIdx.x;  // 128

    __shared__ int   s_idx[KNBR];
    __shared__ float s_xj[KNBR][INC];
    __shared__ float s_attr[KNBR][3];
    __shared__ float s_h[KNBR][HID];
    __shared__ float s_pn[3];

    const int* idx = g_idx[br];
    const float* w1 = br ? w1f : w1g;
    const float* b1 = br ? b1f : b1g;

    if (t < KNBR) s_idx[t] = idx[n * KNBR + t];
    if (t < 3)    s_pn[t] = pos[n * 3 + t];
    __syncthreads();

    for (int v = t; v < KNBR * INC; v += 128)
        s_xj[v / INC][v % INC] = x[(size_t)s_idx[v / INC] * INC + (v % INC)];

    if (t < KNBR) {
        int sj = s_idx[t];
        float cx = pos[sj * 3 + 0] - s_pn[0];
        float cy = pos[sj * 3 + 1] - s_pn[1];
        float cz = pos[sj * 3 + 2] - s_pn[2];
        float rho = sqrtf((cx * cx + cy * cy) + cz * cz);
        float th  = atan2f(cy, cx);
        float ratio = cz / fmaxf(rho, 1e-12f);
        ratio = fminf(1.0f, fmaxf(-1.0f, ratio));
        float ph = acosf(ratio);
        s_attr[t][0] = rho; s_attr[t][1] = th; s_attr[t][2] = ph;
    }
    __syncthreads();

    {   // fnet layer 1 + tanh: thread t owns channel c = t
        int c = t;
        float wa = w1[c], wb = w1[HID + c], wc = w1[2 * HID + c], bb = b1[c];
        float hk[KNBR];
#pragma unroll
        for (int k = 0; k < KNBR; k++)
            hk[k] = tanhf(bb + s_attr[k][0] * wa + s_attr[k][1] * wb + s_attr[k][2] * wc);
#pragma unroll
        for (int k = 0; k < KNBR; k++) s_h[k][c] = hk[k];
    }
    __syncthreads();

    // S[c][i] = sum_k h[k][c] * xj[k][i]; coalesced writes (lane = i)
    int w = t >> 5, lane = t & 31;
    float* Sout = g_S[br] + (size_t)n * SDIM;
    for (int j = 0; j < 32; j++) {
        int c = w * 32 + j;
        float s = 0.f;
#pragma unroll
        for (int k = 0; k < KNBR; k++) s = fmaf(s_h[k][c], s_xj[k][lane], s);
        Sout[c * INC + lane] = s;
    }
    if (t < INC) {
        float m = 0.f;
#pragma unroll
        for (int k = 0; k < KNBR; k++) m += s_xj[k][t];
        g_xjm[br][n * INC + t] = m * (1.0f / 9.0f);
    }
}

// ---------------- 4) GEMM: part[br] = S[br] @ W2[br]  (32x64 tile, 4x4 regs) ---
__global__ __launch_bounds__(128) void gemm_kernel(
    const float* __restrict__ w2g, const float* __restrict__ w2f) {
    __shared__ float Asr[32][17];   // [node][kk], pad 17: conflict-free
    __shared__ float Bs[16][64];

    int tid = threadIdx.x;
    int tx = tid & 15, ty = tid >> 4;       // tx: out-quads, ty: node-quads
    int br = blockIdx.y;
    int n0 = blockIdx.x * 32;
    const float* Sb = g_S[br] + (size_t)n0 * SDIM;
    const float* W  = br ? w2f : w2g;       // row-major [4096][64] since k = c*32+i

    float acc[4][4];
#pragma unroll
    for (int r = 0; r < 4; r++)
#pragma unroll
        for (int c = 0; c < 4; c++) acc[r][c] = 0.f;

    int am = tid >> 2;                // 0..31: node row for A staging
    int ak = (tid & 3) << 2;          // 0,4,8,12: k sub-col

    for (int k0 = 0; k0 < SDIM; k0 += 16) {
        // stage A: each thread one float4 (32 rows x 16 k)
        float4 av = *reinterpret_cast<const float4*>(&Sb[(size_t)am * SDIM + k0 + ak]);
        Asr[am][ak + 0] = av.x; Asr[am][ak + 1] = av.y;
        Asr[am][ak + 2] = av.z; Asr[am][ak + 3] = av.w;
        // stage B: 1024 contiguous floats (k-major rows of 64)
        {
            const float* Wc = W + (size_t)k0 * 64;
#pragma unroll
            for (int v = tid; v < 1024; v += 128) Bs[v >> 6][v & 63] = Wc[v];
        }
        __syncthreads();
#pragma unroll
        for (int kk = 0; kk < 16; kk++) {
            float4 b = *reinterpret_cast<const float4*>(&Bs[kk][tx << 2]);
            float a0 = Asr[(ty << 2) + 0][kk];
            float a1 = Asr[(ty << 2) + 1][kk];
            float a2 = Asr[(ty << 2) + 2][kk];
            float a3 = Asr[(ty << 2) + 3][kk];
            acc[0][0] = fmaf(a0, b.x, acc[0][0]); acc[0][1] = fmaf(a0, b.y, acc[0][1]);
            acc[0][2] = fmaf(a0, b.z, acc[0][2]); acc[0][3] = fmaf(a0, b.w, acc[0][3]);
            acc[1][0] = fmaf(a1, b.x, acc[1][0]); acc[1][1] = fmaf(a1, b.y, acc[1][1]);
            acc[1][2] = fmaf(a1, b.z, acc[1][2]); acc[1][3] = fmaf(a1, b.w, acc[1][3]);
            acc[2][0] = fmaf(a2, b.x, acc[2][0]); acc[2][1] = fmaf(a2, b.y, acc[2][1]);
            acc[2][2] = fmaf(a2, b.z, acc[2][2]); acc[2][3] = fmaf(a2, b.w, acc[2][3]);
            acc[3][0] = fmaf(a3, b.x, acc[3][0]); acc[3][1] = fmaf(a3, b.y, acc[3][1]);
            acc[3][2] = fmaf(a3, b.z, acc[3][2]); acc[3][3] = fmaf(a3, b.w, acc[3][3]);
        }
        __syncthreads();
    }

    float* P = g_part + ((size_t)br * NND + n0) * OUTC;
#pragma unroll
    for (int r = 0; r < 4; r++) {
        float4 v = make_float4(acc[r][0], acc[r][1], acc[r][2], acc[r][3]);
        *reinterpret_cast<float4*>(&P[((ty << 2) + r) * OUTC + (tx << 2)]) = v;
    }
}

// ---------------- 5) combine: out = 0.5*((pg+pf)/9 + xmg@b2g + xmf@b2f) --------
__global__ __launch_bounds__(256) void combine_kernel(
    const float* __restrict__ b2g, const float* __restrict__ b2f,
    float* __restrict__ out) {
    __shared__ float s_b2[2][INC * OUTC];   // 16 KB
    __shared__ float s_xm[2][4][INC];

    int tid = threadIdx.x;
    int nl = tid >> 6, o = tid & 63;
    int n = blockIdx.x * 4 + nl;

    for (int v = tid; v < INC * OUTC; v += 256) {
        s_b2[0][v] = b2g[v];
        s_b2[1][v] = b2f[v];
    }
    {
        int br = tid >> 7, nn = (tid >> 5) & 3, i = tid & 31;
        s_xm[br][nn][i] = g_xjm[br][(size_t)(blockIdx.x * 4 + nn) * INC + i];
    }
    __syncthreads();

    float val = (g_part[(size_t)n * OUTC + o] +
                 g_part[(size_t)(NND + n) * OUTC + o]) * (1.0f / 9.0f);
#pragma unroll
    for (int br = 0; br < 2; br++)
#pragma unroll
        for (int i = 0; i < INC; i++)
            val = fmaf(s_xm[br][nl][i], s_b2[br][i * OUTC + o], val);
    out[(size_t)n * OUTC + o] = 0.5f * val;
}

// ---------------- launch -------------------------------------------------------
extern "C" void kernel_launch(void* const* d_in, const int* in_sizes, int n_in,
                              void* d_out, int out_size) {
    const float* x   = (const float*)d_in[0];
    const float* pos = (const float*)d_in[1];
    const float* w1g = (const float*)d_in[2];
    const float* b1g = (const float*)d_in[3];
    const float* w2g = (const float*)d_in[4];
    const float* b2g = (const float*)d_in[5];
    const float* w1f = (const float*)d_in[6];
    const float* b1f = (const float*)d_in[7];
    const float* w2f = (const float*)d_in[8];
    const float* b2f = (const float*)d_in[9];
    float* out = (float*)d_out;

    sq_kernel<<<(NND + 255) / 256, 256>>>(pos, x);
    knn_pos_kernel<<<NND / 8, 256>>>(pos);
    knn_feat_kernel<<<NND / 16, 256>>>(x);
    buildS_kernel<<<dim3(NND, 2), 128>>>(x, pos, w1g, b1g, w1f, b1f);
    gemm_kernel<<<dim3(NND / 32, 2), 128>>>(w2g, w2f);
    combine_kernel<<<NND / 4, 256>>>(b2g, b2f, out);
}

// round 3
// speedup vs baseline: 2.0095x; 1.0011x over previous
#include <cuda_runtime.h>
#include <math.h>
#include <stdint.h>

#define NND   4096
#define KNBR  9
#define INC   32
#define OUTC  64
#define HID   128
#define SDIM  4096   // HID * INC

// ---------------- scratch (static device globals; no allocation) ----------------
__device__ int   g_idx[2][NND * KNBR];
__device__ float g_S[2][(size_t)NND * SDIM];          // 2 x 64 MB
__device__ float g_xjm[2][NND * INC];
__device__ float g_part[2 * NND * OUTC];              // per-branch GEMM partials

// Order matches jax.lax.top_k(-d): ascending d, ties -> ascending index.
__device__ __forceinline__ bool knn_less(float d, int i, float d2, int i2) {
    return (d < d2) || (d == d2 && i < i2);
}

__device__ __forceinline__ void knn_insert(float dist, int j, float bd[KNBR], int bi[KNBR]) {
    if (knn_less(dist, j, bd[KNBR - 1], bi[KNBR - 1])) {
        float cd = dist; int ci = j;
#pragma unroll
        for (int r = 0; r < KNBR; r++) {
            bool sw = knn_less(cd, ci, bd[r], bi[r]);
            float td = bd[r]; int ti = bi[r];
            if (sw) { bd[r] = cd; bi[r] = ci; cd = td; ci = ti; }
        }
    }
}

// Warp-wide 9-round merge of per-lane sorted lists (smem-backed, per-warp region).
__device__ __forceinline__ void knn_merge(float* md, int* mi, const float bd[KNBR],
                                          const int bi[KNBR], int lane, int* oidx, int q) {
#pragma unroll
    for (int r = 0; r < KNBR; r++) { md[lane * KNBR + r] = bd[r]; mi[lane * KNBR + r] = bi[r]; }
    __syncwarp();
    int p = 0;
    for (int r = 0; r < KNBR; r++) {
        float cd = (p < KNBR) ? md[lane * KNBR + p] : 3.4e38f;
        int   ci = (p < KNBR) ? mi[lane * KNBR + p] : 0x7FFFFFFF;
        float rd = cd; int ri = ci;
#pragma unroll
        for (int off = 16; off; off >>= 1) {
            float od = __shfl_xor_sync(0xFFFFFFFFu, rd, off);
            int   oi = __shfl_xor_sync(0xFFFFFFFFu, ri, off);
            if (knn_less(od, oi, rd, ri)) { rd = od; ri = oi; }
        }
        if (ci == ri && p < KNBR) p++;   // candidate indices unique per lane
        if (lane == 0) oidx[q * KNBR + r] = ri;
    }
    __syncwarp();
}

// ---------------- 1) KNN on pos (dim 3): whole pos in smem, norms inline -------
__global__ __launch_bounds__(256) void knn_pos_kernel(const float* __restrict__ pos) {
    __shared__ float smem[NND * 3];   // 48 KB; merge overlay after
    int t = threadIdx.x, w = t >> 5, lane = t & 31;
    int q = blockIdx.x * 8 + w;

    for (int v = t; v < NND * 3; v += 256) smem[v] = pos[v];
    __syncthreads();

    float q0 = smem[q * 3 + 0], q1 = smem[q * 3 + 1], q2 = smem[q * 3 + 2];
    // query sq: identical fmaf chain as candidate sq below -> self-dist exact 0
    float sqq = 0.f;
    sqq = fmaf(q0, q0, sqq); sqq = fmaf(q1, q1, sqq); sqq = fmaf(q2, q2, sqq);

    float bd[KNBR]; int bi[KNBR];
#pragma unroll
    for (int r = 0; r < KNBR; r++) { bd[r] = 3.4e38f; bi[r] = 0x7FFFFFFF; }

    for (int j = lane; j < NND; j += 32) {
        float c0 = smem[j * 3 + 0], c1 = smem[j * 3 + 1], c2 = smem[j * 3 + 2];
        float acc = 0.f;
        acc = fmaf(q0, c0, acc); acc = fmaf(q1, c1, acc); acc = fmaf(q2, c2, acc);
        float sqj = 0.f;
        sqj = fmaf(c0, c0, sqj); sqj = fmaf(c1, c1, sqj); sqj = fmaf(c2, c2, sqj);
        float dist = (sqq + sqj) - 2.0f * acc;
        knn_insert(dist, j, bd, bi);
    }
    __syncthreads();   // all warps done reading smem before merge overlay

    float* md = smem + (size_t)w * 288;
    int*   mi = (int*)(smem + 8 * 288) + (size_t)w * 288;
    knn_merge(md, mi, bd, bi, lane, g_idx[0], q);
}

// ---------------- 2) KNN on x (dim 32): tiled smem, 2 queries/warp -------------
#define TS 256
__global__ __launch_bounds__(256) void knn_feat_kernel(const float* __restrict__ x) {
    __shared__ float s_tile[TS * 33];   // stride-33 pad: conflict-free
    __shared__ float s_sq[TS];
    int t = threadIdx.x, w = t >> 5, lane = t & 31;
    int qa_i = blockIdx.x * 16 + w * 2;
    int qb_i = qa_i + 1;

    float qa[INC], qb[INC];
#pragma unroll
    for (int d = 0; d < INC; d++) qa[d] = x[qa_i * INC + d];
#pragma unroll
    for (int d = 0; d < INC; d++) qb[d] = x[qb_i * INC + d];
    float sqa = 0.f, sqb = 0.f;
#pragma unroll
    for (int d = 0; d < INC; d++) sqa = fmaf(qa[d], qa[d], sqa);
#pragma unroll
    for (int d = 0; d < INC; d++) sqb = fmaf(qb[d], qb[d], sqb);

    float bda[KNBR], bdb[KNBR]; int bia[KNBR], bib[KNBR];
#pragma unroll
    for (int r = 0; r < KNBR; r++) {
        bda[r] = 3.4e38f; bia[r] = 0x7FFFFFFF;
        bdb[r] = 3.4e38f; bib[r] = 0x7FFFFFFF;
    }

    for (int base = 0; base < NND; base += TS) {
        __syncthreads();
#pragma unroll
        for (int v = t; v < TS * INC; v += 256) {
            int r = v >> 5, d = v & 31;
            s_tile[r * 33 + d] = x[(size_t)(base + r) * INC + d];
        }
        __syncthreads();
        {   // per-row sq with identical fmaf chain (thread t owns row t)
            float s = 0.f;
#pragma unroll
            for (int d = 0; d < INC; d++) { float v = s_tile[t * 33 + d]; s = fmaf(v, v, s); }
            s_sq[t] = s;
        }
        __syncthreads();

        for (int s = 0; s < TS; s += 32) {
            int r = s + lane;
            int j = base + r;
            const float* c = &s_tile[r * 33];
            float acc0 = 0.f, acc1 = 0.f;
#pragma unroll
            for (int d = 0; d < INC; d++) {
                float cv = c[d];
                acc0 = fmaf(qa[d], cv, acc0);
                acc1 = fmaf(qb[d], cv, acc1);
            }
            float sqj = s_sq[r];
            knn_insert((sqa + sqj) - 2.0f * acc0, j, bda, bia);
            knn_insert((sqb + sqj) - 2.0f * acc1, j, bdb, bib);
        }
    }
    __syncthreads();   // done with s_tile; safe to overlay merge buffers

    float* md = s_tile + (size_t)w * 288;
    int*   mi = (int*)(s_tile + 8 * 288) + (size_t)w * 288;
    knn_merge(md, mi, bda, bia, lane, g_idx[1], qa_i);
    knn_merge(md, mi, bdb, bib, lane, g_idx[1], qb_i);
}

// ---------------- 3) per-(node, branch): attrs -> h -> S, xjmean ---------------
__global__ __launch_bounds__(128) void buildS_kernel(
    const float* __restrict__ x, const float* __restrict__ pos,
    const float* __restrict__ w1g, const float* __restrict__ b1g,
    const float* __restrict__ w1f, const float* __restrict__ b1f) {
    int n = blockIdx.x, br = blockIdx.y;
    int t = threadIdx.x;  // 128

    __shared__ int   s_idx[KNBR];
    __shared__ float s_xj[KNBR][INC];
    __shared__ float s_attr[KNBR][3];
    __shared__ float s_h[KNBR][HID];
    __shared__ float s_pn[3];

    const int* idx = g_idx[br];
    const float* w1 = br ? w1f : w1g;
    const float* b1 = br ? b1f : b1g;

    if (t < KNBR) s_idx[t] = idx[n * KNBR + t];
    if (t < 3)    s_pn[t] = pos[n * 3 + t];
    __syncthreads();

    for (int v = t; v < KNBR * INC; v += 128)
        s_xj[v / INC][v % INC] = x[(size_t)s_idx[v / INC] * INC + (v % INC)];

    if (t < KNBR) {
        int sj = s_idx[t];
        float cx = pos[sj * 3 + 0] - s_pn[0];
        float cy = pos[sj * 3 + 1] - s_pn[1];
        float cz = pos[sj * 3 + 2] - s_pn[2];
        float rho = sqrtf((cx * cx + cy * cy) + cz * cz);
        float th  = atan2f(cy, cx);
        float ratio = cz / fmaxf(rho, 1e-12f);
        ratio = fminf(1.0f, fmaxf(-1.0f, ratio));
        float ph = acosf(ratio);
        s_attr[t][0] = rho; s_attr[t][1] = th; s_attr[t][2] = ph;
    }
    __syncthreads();

    {   // fnet layer 1 + tanh: thread t owns channel c = t
        int c = t;
        float wa = w1[c], wb = w1[HID + c], wc = w1[2 * HID + c], bb = b1[c];
        float hk[KNBR];
#pragma unroll
        for (int k = 0; k < KNBR; k++)
            hk[k] = tanhf(bb + s_attr[k][0] * wa + s_attr[k][1] * wb + s_attr[k][2] * wc);
#pragma unroll
        for (int k = 0; k < KNBR; k++) s_h[k][c] = hk[k];
    }
    __syncthreads();

    // S[c][i] = sum_k h[k][c] * xj[k][i]; coalesced writes (lane = i)
    int w = t >> 5, lane = t & 31;
    float* Sout = g_S[br] + (size_t)n * SDIM;
    for (int j = 0; j < 32; j++) {
        int c = w * 32 + j;
        float s = 0.f;
#pragma unroll
        for (int k = 0; k < KNBR; k++) s = fmaf(s_h[k][c], s_xj[k][lane], s);
        Sout[c * INC + lane] = s;
    }
    if (t < INC) {
        float m = 0.f;
#pragma unroll
        for (int k = 0; k < KNBR; k++) m += s_xj[k][t];
        g_xjm[br][n * INC + t] = m * (1.0f / 9.0f);
    }
}

// ---------------- 4) GEMM: part[br] = S[br] @ W2[br] ---------------------------
// 32 nodes x 64 outs per block, 256 threads, KC=32, double-buffered smem.
#define KC 32
__global__ __launch_bounds__(256) void gemm_kernel(
    const float* __restrict__ w2g, const float* __restrict__ w2f) {
    __shared__ float As[2][KC][33];   // [k][node] transposed, pad-33 conflict-free
    __shared__ float Bs[2][KC][64];

    int tid = threadIdx.x;
    int tx = tid & 15, ty = tid >> 4;       // tx: out-quad, ty: node-pair
    int br = blockIdx.y;
    int n0 = blockIdx.x * 32;
    const float* Sb = g_S[br] + (size_t)n0 * SDIM;
    const float* W  = br ? w2f : w2g;       // row-major [4096 k][64 o]

    // staging maps
    int anode = tid >> 3;                   // 0..31
    int akq   = (tid & 7) * 4;              // 0,4,...,28
    int bk    = tid >> 3;                   // 0..31
    int bo    = (tid & 7) * 8;              // 0,8,...,56

    float acc[2][4];
#pragma unroll
    for (int r = 0; r < 2; r++)
#pragma unroll
        for (int c = 0; c < 4; c++) acc[r][c] = 0.f;

    // prologue: chunk 0 -> regs -> buf 0
    float4 aReg = *reinterpret_cast<const float4*>(&Sb[(size_t)anode * SDIM + akq]);
    float4 bReg0 = *reinterpret_cast<const float4*>(&W[(size_t)bk * 64 + bo]);
    float4 bReg1 = *reinterpret_cast<const float4*>(&W[(size_t)bk * 64 + bo + 4]);
    As[0][akq + 0][anode] = aReg.x; As[0][akq + 1][anode] = aReg.y;
    As[0][akq + 2][anode] = aReg.z; As[0][akq + 3][anode] = aReg.w;
    *reinterpret_cast<float4*>(&Bs[0][bk][bo])     = bReg0;
    *reinterpret_cast<float4*>(&Bs[0][bk][bo + 4]) = bReg1;

    int p = 0;
    for (int c = 0; c < SDIM / KC; c++) {
        __syncthreads();
        if (c + 1 < SDIM / KC) {
            int k0 = (c + 1) * KC;
            aReg  = *reinterpret_cast<const float4*>(&Sb[(size_t)anode * SDIM + k0 + akq]);
            bReg0 = *reinterpret_cast<const float4*>(&W[(size_t)(k0 + bk) * 64 + bo]);
            bReg1 = *reinterpret_cast<const float4*>(&W[(size_t)(k0 + bk) * 64 + bo + 4]);
        }
#pragma unroll
        for (int kk = 0; kk < KC; kk++) {
            float a0 = As[p][kk][ty * 2 + 0];
            float a1 = As[p][kk][ty * 2 + 1];
            float4 b = *reinterpret_cast<const float4*>(&Bs[p][kk][tx * 4]);
            acc[0][0] = fmaf(a0, b.x, acc[0][0]); acc[0][1] = fmaf(a0, b.y, acc[0][1]);
            acc[0][2] = fmaf(a0, b.z, acc[0][2]); acc[0][3] = fmaf(a0, b.w, acc[0][3]);
            acc[1][0] = fmaf(a1, b.x, acc[1][0]); acc[1][1] = fmaf(a1, b.y, acc[1][1]);
            acc[1][2] = fmaf(a1, b.z, acc[1][2]); acc[1][3] = fmaf(a1, b.w, acc[1][3]);
        }
        if (c + 1 < SDIM / KC) {
            int q = p ^ 1;
            As[q][akq + 0][anode] = aReg.x; As[q][akq + 1][anode] = aReg.y;
            As[q][akq + 2][anode] = aReg.z; As[q][akq + 3][anode] = aReg.w;
            *reinterpret_cast<float4*>(&Bs[q][bk][bo])     = bReg0;
            *reinterpret_cast<float4*>(&Bs[q][bk][bo + 4]) = bReg1;
        }
        p ^= 1;
    }

    float* P = g_part + ((size_t)br * NND + n0) * OUTC;
#pragma unroll
    for (int r = 0; r < 2; r++) {
        float4 v = make_float4(acc[r][0], acc[r][1], acc[r][2], acc[r][3]);
        *reinterpret_cast<float4*>(&P[(ty * 2 + r) * OUTC + tx * 4]) = v;
    }
}

// ---------------- 5) combine: out = 0.5*((pg+pf)/9 + xmg@b2g + xmf@b2f) --------
__global__ __launch_bounds__(256) void combine_kernel(
    const float* __restrict__ b2g, const float* __restrict__ b2f,
    float* __restrict__ out) {
    __shared__ float s_b2[2][INC * OUTC];   // 16 KB
    __shared__ float s_xm[2][4][INC];

    int tid = threadIdx.x;
    int nl = tid >> 6, o = tid & 63;
    int n = blockIdx.x * 4 + nl;

    for (int v = tid; v < INC * OUTC; v += 256) {
        s_b2[0][v] = b2g[v];
        s_b2[1][v] = b2f[v];
    }
    {
        int br = tid >> 7, nn = (tid >> 5) & 3, i = tid & 31;
        s_xm[br][nn][i] = g_xjm[br][(size_t)(blockIdx.x * 4 + nn) * INC + i];
    }
    __syncthreads();

    float val = (g_part[(size_t)n * OUTC + o] +
                 g_part[(size_t)(NND + n) * OUTC + o]) * (1.0f / 9.0f);
#pragma unroll
    for (int br = 0; br < 2; br++)
#pragma unroll
        for (int i = 0; i < INC; i++)
            val = fmaf(s_xm[br][nl][i], s_b2[br][i * OUTC + o], val);
    out[(size_t)n * OUTC + o] = 0.5f * val;
}

// ---------------- launch -------------------------------------------------------
extern "C" void kernel_launch(void* const* d_in, const int* in_sizes, int n_in,
                              void* d_out, int out_size) {
    const float* x   = (const float*)d_in[0];
    const float* pos = (const float*)d_in[1];
    const float* w1g = (const float*)d_in[2];
    const float* b1g = (const float*)d_in[3];
    const float* w2g = (const float*)d_in[4];
    const float* b2g = (const float*)d_in[5];
    const float* w1f = (const float*)d_in[6];
    const float* b1f = (const float*)d_in[7];
    const float* w2f = (const float*)d_in[8];
    const float* b2f = (const float*)d_in[9];
    float* out = (float*)d_out;

    knn_pos_kernel<<<NND / 8, 256>>>(pos);
    knn_feat_kernel<<<NND / 16, 256>>>(x);
    buildS_kernel<<<dim3(NND, 2), 128>>>(x, pos, w1g, b1g, w1f, b1f);
    gemm_kernel<<<dim3(NND / 32, 2), 256>>>(w2g, w2f);
    combine_kernel<<<NND / 4, 256>>>(b2g, b2f, out);
}